// round 2
// baseline (speedup 1.0000x reference)
#include <cuda_runtime.h>
#include <cstdint>

#define N_SAMP 16
#define C_TOT 256
#define KK 8
#define M_IN 63
#define M_OUT 56
#define GROUPS 32          // channel groups of 8 channels (4 pairs)
#define PAIRS 4            // channel pairs per group
#define THREADS 224        // 56 cols x 4 row-bands
#define R_ROWS 14          // output rows per thread
#define OUT_PER_N (M_OUT * M_OUT)   // 3136
#define OUT_TOTAL (N_SAMP * OUT_PER_N)
#define XS_F2 (M_IN * 64)  // one x buffer: 63 rows x 64 float2 (col 63 pad)
#define ZS_F2 (PAIRS * KK * KK)
#define SMEM_BYTES ((2 * XS_F2 + ZS_F2) * (int)sizeof(float2))  // 66560

typedef unsigned long long ull;

// Partial sums: [group][n][i*56+j]  (32 * 16 * 3136 floats = 6.4 MB)
__device__ float g_partial[GROUPS * OUT_TOTAL];

__device__ __forceinline__ ull fma2(ull a, ull b, ull c) {
    ull d;
    asm("fma.rn.f32x2 %0, %1, %2, %3;" : "=l"(d) : "l"(a), "l"(b), "l"(c));
    return d;
}

__device__ __forceinline__ float fast_sqrt(float v) {
    float r;
    asm("sqrt.approx.f32 %0, %1;" : "=f"(r) : "f"(v));
    return r;
}

// Stage sqrt of 2 consecutive channels (contiguous 7938-float stream at xc,
// 8B-aligned) into dst interleaved as float2 pairs: dst[row*64+col] = (c0, c1).
__device__ __forceinline__ void stage_x(float2* __restrict__ dst,
                                        const float* __restrict__ xc, int tid)
{
    const float2* src = reinterpret_cast<const float2*>(xc);
    #pragma unroll
    for (int it = 0; it < 18; it++) {
        int i = tid + it * THREADS;              // float2 index, 3969 total
        if (i < 3969) {
            float2 v = src[i];
            int e0 = 2 * i, e1 = 2 * i + 1;
            int ch0 = (e0 >= 3969) ? 1 : 0;
            int ch1 = (e1 >= 3969) ? 1 : 0;
            int pos0 = e0 - ch0 * 3969;
            int pos1 = e1 - ch1 * 3969;
            int r0 = pos0 / M_IN, c0 = pos0 - r0 * M_IN;
            int r1 = pos1 / M_IN, c1 = pos1 - r1 * M_IN;
            reinterpret_cast<float*>(&dst[r0 * 64 + c0])[ch0] = fast_sqrt(v.x);
            reinterpret_cast<float*>(&dst[r1 * 64 + c1])[ch1] = fast_sqrt(v.y);
        }
    }
}

__global__ __launch_bounds__(THREADS, 3)
void conv_partial_kernel(const float* __restrict__ z,
                         const float* __restrict__ x,
                         const float* __restrict__ w)
{
    extern __shared__ float2 smem[];
    float2* xs0 = smem;
    float2* xs1 = smem + XS_F2;
    float2* zs  = smem + 2 * XS_F2;          // [pair][p*8+q]

    const int n   = blockIdx.x;
    const int g   = blockIdx.y;
    const int tid = threadIdx.x;
    const int j   = tid % M_OUT;
    const int i0  = (tid / M_OUT) * R_ROWS;

    const int cbase = g * (2 * PAIRS);
    const float* xn = x + (size_t)n * C_TOT * (M_IN * M_IN);
    const float* zn = z + (size_t)n * C_TOT * (KK * KK);

    // Stage all z (w*sqrt(z) channel pairs) once
    for (int idx = tid; idx < ZS_F2; idx += THREADS) {
        int cp  = idx >> 6;
        int tap = idx & 63;
        int c   = cbase + 2 * cp;
        float w0 = w[c], w1 = w[c + 1];
        float a = fast_sqrt(zn[(size_t)c * 64 + tap]);
        float b = fast_sqrt(zn[(size_t)(c + 1) * 64 + tap]);
        zs[idx] = make_float2(w0 * a, w1 * b);
    }
    // Stage x pair 0 into buffer 0
    stage_x(xs0, xn + (size_t)cbase * (M_IN * M_IN), tid);
    __syncthreads();

    ull acc[R_ROWS];
    #pragma unroll
    for (int r = 0; r < R_ROWS; r++) acc[r] = 0ULL;

    #pragma unroll
    for (int cp = 0; cp < PAIRS; cp++) {
        float2* cur = (cp & 1) ? xs1 : xs0;
        float2* nxt = (cp & 1) ? xs0 : xs1;

        // Prefetch next pair into the other buffer (overlaps with compute of
        // other warps/CTAs; guarded by the barrier at loop end).
        if (cp + 1 < PAIRS)
            stage_x(nxt, xn + (size_t)(cbase + 2 * (cp + 1)) * (M_IN * M_IN), tid);

        const float2* xrow = cur + i0 * 64 + j;
        const float2* zsp  = zs + cp * (KK * KK);

        #pragma unroll
        for (int q = 0; q < KK; q++) {
            ull zq[KK];
            #pragma unroll
            for (int p = 0; p < KK; p++)
                zq[p] = *reinterpret_cast<const ull*>(&zsp[p * KK + q]);

            #pragma unroll
            for (int t = 0; t < R_ROWS + KK - 1; t++) {
                ull xv = *reinterpret_cast<const ull*>(xrow + t * 64 + q);
                #pragma unroll
                for (int r = 0; r < R_ROWS; r++) {
                    const int p = t - r;
                    if (p >= 0 && p < KK)
                        acc[r] = fma2(xv, zq[p], acc[r]);
                }
            }
        }
        __syncthreads();
    }

    float* outp = g_partial + (size_t)(g * N_SAMP + n) * OUT_PER_N;
    #pragma unroll
    for (int r = 0; r < R_ROWS; r++) {
        float lo = __uint_as_float((unsigned)(acc[r] & 0xFFFFFFFFull));
        float hi = __uint_as_float((unsigned)(acc[r] >> 32));
        outp[(i0 + r) * M_OUT + j] = lo + hi;
    }
}

__global__ void reduce_kernel(float4* __restrict__ out)
{
    int idx = blockIdx.x * blockDim.x + threadIdx.x;   // 12544 float4
    if (idx >= OUT_TOTAL / 4) return;
    const float4* p = reinterpret_cast<const float4*>(g_partial);
    float4 s = make_float4(0.f, 0.f, 0.f, 0.f);
    #pragma unroll
    for (int g = 0; g < GROUPS; g++) {
        float4 v = p[(size_t)g * (OUT_TOTAL / 4) + idx];
        s.x += v.x; s.y += v.y; s.z += v.z; s.w += v.w;
    }
    const float sc = 1.0f / (KK * KK);
    out[idx] = make_float4(s.x * sc, s.y * sc, s.z * sc, s.w * sc);
}

extern "C" void kernel_launch(void* const* d_in, const int* in_sizes, int n_in,
                              void* d_out, int out_size)
{
    const float* z = (const float*)d_in[0];   // (16,256,8,8)
    const float* x = (const float*)d_in[1];   // (16,256,63,63)
    const float* w = (const float*)d_in[2];   // (1,256,1,1,1)
    float4* out = (float4*)d_out;             // (16,1,56,56)

    cudaFuncSetAttribute(conv_partial_kernel,
                         cudaFuncAttributeMaxDynamicSharedMemorySize, SMEM_BYTES);

    dim3 grid(N_SAMP, GROUPS);
    conv_partial_kernel<<<grid, THREADS, SMEM_BYTES>>>(z, x, w);
    reduce_kernel<<<(OUT_TOTAL / 4 + 255) / 256, 256>>>(out);
}

// round 4
// speedup vs baseline: 1.0741x; 1.0741x over previous
#include <cuda_runtime.h>
#include <cstdint>

#define N_SAMP 16
#define C_TOT 256
#define KK 8
#define M_IN 63
#define M_OUT 56
#define CHUNKS 16          // channel chunks (16 channels = 8 pairs each)
#define PAIRS 8
#define THREADS 224        // 56 cols x 4 row-bands
#define R_ROWS 14
#define OUT_PER_N (M_OUT * M_OUT)   // 3136
#define OUT_TOTAL (N_SAMP * OUT_PER_N)
#define PLANE 3969         // 63*63 floats per channel
#define RAW_FLOATS (2 * PLANE)      // one raw pair buffer: 7938 floats
#define XS_F2 (M_IN * 64)           // 63 rows x 64 float2 (col 63 pad)

typedef unsigned long long ull;

__device__ float g_partial[CHUNKS * OUT_TOTAL];   // 3.2 MB scratch

__device__ __forceinline__ ull fma2(ull a, ull b, ull c) {
    ull d;
    asm("fma.rn.f32x2 %0, %1, %2, %3;" : "=l"(d) : "l"(a), "l"(b), "l"(c));
    return d;
}
__device__ __forceinline__ float fast_sqrt(float v) {
    float r;
    asm("sqrt.approx.f32 %0, %1;" : "=f"(r) : "f"(v));
    return r;
}
__device__ __forceinline__ void cp_async8(uint32_t saddr, const void* gaddr) {
    asm volatile("cp.async.ca.shared.global [%0], [%1], 8;\n"
                 :: "r"(saddr), "l"(gaddr));
}
__device__ __forceinline__ void cp_commit() {
    asm volatile("cp.async.commit_group;\n" ::: "memory");
}
__device__ __forceinline__ void cp_wait0() {
    asm volatile("cp.async.wait_group 0;\n" ::: "memory");
}
__device__ __forceinline__ void cp_wait1() {
    asm volatile("cp.async.wait_group 1;\n" ::: "memory");
}

// Issue async copy of one channel pair (7938 floats, 8B-aligned) into raw buf.
__device__ __forceinline__ void issue_pair(uint32_t raw_s, const float* xc, int tid)
{
    #pragma unroll
    for (int it = 0; it < 18; it++) {
        int i = tid + it * THREADS;            // 8-byte unit index, 3969 total
        if (i < PLANE)
            cp_async8(raw_s + i * 8, (const char*)xc + i * 8);
    }
    cp_commit();
}

// raw (2 channel planes) -> xs interleaved sqrt pairs
__device__ __forceinline__ void convert_pair(const float* __restrict__ raw,
                                             float2* __restrict__ xs, int tid)
{
    #pragma unroll
    for (int it = 0; it < 18; it++) {
        int pos = tid + it * THREADS;
        if (pos < PLANE) {
            float f0 = raw[pos];
            float f1 = raw[PLANE + pos];
            int row = pos / M_IN;
            int col = pos - row * M_IN;
            xs[row * 64 + col] = make_float2(fast_sqrt(f0), fast_sqrt(f1));
        }
    }
}

__global__ __launch_bounds__(THREADS, 2)
void conv_partial_kernel(const float* __restrict__ z,
                         const float* __restrict__ x,
                         const float* __restrict__ w)
{
    extern __shared__ float smem_raw[];
    float2* xs   = reinterpret_cast<float2*>(smem_raw);          // 32256 B
    float*  raw0 = smem_raw + 2 * XS_F2;                         // 31752 B
    float*  raw1 = raw0 + RAW_FLOATS;                            // 31752 B
    float2* zs   = reinterpret_cast<float2*>(raw1 + RAW_FLOATS); // 4096 B

    const int n     = blockIdx.x;
    const int chunk = blockIdx.y;
    const int tid   = threadIdx.x;
    const int j     = tid % M_OUT;
    const int i0    = (tid / M_OUT) * R_ROWS;

    const int cbase = chunk * (2 * PAIRS);
    const float* xn = x + (size_t)n * C_TOT * (M_IN * M_IN);
    const float* zn = z + (size_t)n * C_TOT * (KK * KK);

    const uint32_t raw0_s = (uint32_t)__cvta_generic_to_shared(raw0);
    const uint32_t raw1_s = (uint32_t)__cvta_generic_to_shared(raw1);

    // Pipeline prologue: pair0 -> raw0, pair1 -> raw1 (issued first, so the
    // DRAM fetch runs under the z staging below).
    issue_pair(raw0_s, xn + (size_t)cbase * PLANE, tid);
    issue_pair(raw1_s, xn + (size_t)(cbase + 2) * PLANE, tid);

    // Stage all z pairs once: zs[pair][p*8+q] = (w0*sqrt(z0), w1*sqrt(z1))
    for (int idx = tid; idx < PAIRS * KK * KK; idx += THREADS) {
        int cp  = idx >> 6;
        int tap = idx & 63;
        int c   = cbase + 2 * cp;
        float w0 = w[c], w1 = w[c + 1];
        float a = fast_sqrt(zn[(size_t)c * 64 + tap]);
        float b = fast_sqrt(zn[(size_t)(c + 1) * 64 + tap]);
        zs[idx] = make_float2(w0 * a, w1 * b);
    }

    cp_wait1();                       // this thread's raw0 copies complete
    __syncthreads();                  // make ALL threads' raw0 copies visible
    convert_pair(raw0, xs, tid);
    __syncthreads();

    ull acc[R_ROWS];
    #pragma unroll
    for (int r = 0; r < R_ROWS; r++) acc[r] = 0ULL;

    #pragma unroll 1
    for (int cp = 0; cp < PAIRS; cp++) {
        const float2* xrow = xs + i0 * 64 + j;
        const float2* zsp  = zs + cp * (KK * KK);

        #pragma unroll
        for (int q = 0; q < KK; q++) {
            ull zq[KK];
            #pragma unroll
            for (int p = 0; p < KK; p++)
                zq[p] = *reinterpret_cast<const ull*>(&zsp[p * KK + q]);

            #pragma unroll
            for (int t = 0; t < R_ROWS + KK - 1; t++) {
                ull xv = *reinterpret_cast<const ull*>(xrow + t * 64 + q);
                #pragma unroll
                for (int r = 0; r < R_ROWS; r++) {
                    const int p = t - r;
                    if (p >= 0 && p < KK)
                        acc[r] = fma2(xv, zq[p], acc[r]);
                }
            }
        }

        if (cp < PAIRS - 1) {
            const float* nraw = (cp & 1) ? raw0 : raw1;     // buf[(cp+1)&1]
            const uint32_t is = (cp & 1) ? raw1_s : raw0_s; // buf[cp&1] for cp+2
            cp_wait0();               // pair cp+1's copies (this thread) done
            __syncthreads();          // visibility across threads; xs reads done
            convert_pair(nraw, xs, tid);
            if (cp < PAIRS - 2)
                issue_pair(is, xn + (size_t)(cbase + 2 * (cp + 2)) * PLANE, tid);
            __syncthreads();          // xs ready for next compute
        }
    }

    float* outp = g_partial + (size_t)(chunk * N_SAMP + n) * OUT_PER_N;
    #pragma unroll
    for (int r = 0; r < R_ROWS; r++) {
        float lo = __uint_as_float((unsigned)(acc[r] & 0xFFFFFFFFull));
        float hi = __uint_as_float((unsigned)(acc[r] >> 32));
        outp[(i0 + r) * M_OUT + j] = lo + hi;
    }
}

__global__ void reduce_kernel(float* __restrict__ out)
{
    int idx = blockIdx.x * blockDim.x + threadIdx.x;
    if (idx >= OUT_TOTAL) return;
    float s = 0.0f;
    #pragma unroll
    for (int ch = 0; ch < CHUNKS; ch++)
        s += g_partial[(size_t)ch * OUT_TOTAL + idx];
    out[idx] = s * (1.0f / (KK * KK));
}

extern "C" void kernel_launch(void* const* d_in, const int* in_sizes, int n_in,
                              void* d_out, int out_size)
{
    const float* z = (const float*)d_in[0];   // (16,256,8,8)
    const float* x = (const float*)d_in[1];   // (16,256,63,63)
    const float* w = (const float*)d_in[2];   // (1,256,1,1,1)
    float* out = (float*)d_out;               // (16,1,56,56)

    static int smem_bytes =
        (2 * XS_F2) * 4 + 2 * RAW_FLOATS * 4 + PAIRS * KK * KK * 8;  // 99856

    cudaFuncSetAttribute(conv_partial_kernel,
                         cudaFuncAttributeMaxDynamicSharedMemorySize, smem_bytes);

    dim3 grid(N_SAMP, CHUNKS);
    conv_partial_kernel<<<grid, THREADS, smem_bytes>>>(z, x, w);
    reduce_kernel<<<(OUT_TOTAL + 255) / 256, 256>>>(out);
}